// round 1
// baseline (speedup 1.0000x reference)
#include <cuda_runtime.h>
#include <cuda_bf16.h>
#include <cstdint>

// Problem constants
#define NN   255          // nodes
#define BB   512          // batch
#define NNZK 2550
#define MAXD 400
#define BIGBUF (130560*MAXD)   // 52,224,000 floats (= B*N*400)

// Scratch (device globals: allocation-free rule)
__device__ float g_bufP[BIGBUF];
__device__ float g_bufQ[BIGBUF];
__device__ float g_Asm[NN*NN];
__device__ float g_Asp[NN*NN];
__device__ float g_rsm[NN];
__device__ float g_rsp[NN];

// ---------------- f32x2 packed-FMA helpers (sm_103a) ----------------
__device__ __forceinline__ unsigned long long pack2(float x, float y) {
    unsigned long long r;
    asm("mov.b64 %0, {%1,%2};" : "=l"(r) : "f"(x), "f"(y));
    return r;
}
__device__ __forceinline__ void fma2(unsigned long long& acc,
                                     unsigned long long a, unsigned long long b) {
    asm("fma.rn.f32x2 %0, %1, %2, %0;" : "+l"(acc) : "l"(a), "l"(b));
}
__device__ __forceinline__ float2 unpack2(unsigned long long v) {
    float2 f;
    asm("mov.b64 {%0,%1}, %2;" : "=f"(f.x), "=f"(f.y) : "l"(v));
    return f;
}

// ---------------- small prep kernels ----------------
__global__ void zero2_k(float* a, float* b, int n) {
    int t = blockIdx.x * blockDim.x + threadIdx.x;
    if (t < n) { a[t] = 0.f; b[t] = 0.f; }
}

__global__ void scatter_k(const int* __restrict__ idx, const float* __restrict__ val,
                          float* __restrict__ A) {
    int t = blockIdx.x * blockDim.x + threadIdx.x;
    if (t < NNZK) atomicAdd(&A[idx[2*t] * NN + idx[2*t+1]], val[t]);
}

__global__ void rowsums_k(const float* __restrict__ Am, const float* __restrict__ Ap,
                          float* rm, float* rp) {
    int i = threadIdx.x;
    if (i < NN) {
        float s = 0.f, t = 0.f;
        for (int j = 0; j < NN; j++) { s += Am[i*NN+j]; t += Ap[i*NN+j]; }
        rm[i] = s; rp[i] = t;
    }
}

// H [B,N,2] row-major -> X [N,B,2]
__global__ void transpose_in_k(const float* __restrict__ H, float* __restrict__ X) {
    int t = blockIdx.x * blockDim.x + threadIdx.x;
    if (t < BB * NN) {
        int b = t / NN, n = t % NN;
        float2 v = *(const float2*)&H[(size_t)t * 2];
        *(float2*)&X[((size_t)n * BB + b) * 2] = v;
    }
}

// ---------------- generic tiled SGEMM with epilogue modes ----------------
// C[M,Ncols] = A[M,K] @ B[K,Ncols]   (all row-major)
// MODE 0: plain store
// MODE 1: + bias[col]
// MODE 2: + rvec[row>>9]*bias[col], relu        (rows are n*512+b)
// MODE 3: relu
// MODE 4: relu, scatter-store to out[b*(N*2) + row*2 + d], col=(b*2+d), Ncols=1024
#define BM 128
#define BN 128
#define BK 16

template<int MODE>
__global__ __launch_bounds__(256, 2)
void sgemm_k(const float* __restrict__ A, const float* __restrict__ B,
             float* __restrict__ C, int M, int Ncols, int K,
             const float* __restrict__ bias, const float* __restrict__ rvec)
{
    __shared__ float As[BK][BM + 4];
    __shared__ float Bs[BK][BN + 4];

    const int tid  = threadIdx.x;
    const int tx   = tid & 15;        // 0..15 -> col group (8 cols)
    const int ty   = tid >> 4;        // 0..15 -> row group (8 rows)
    const int brow = blockIdx.y * BM;
    const int bcol = blockIdx.x * BN;

    unsigned long long acc[8][4];
#pragma unroll
    for (int i = 0; i < 8; i++)
#pragma unroll
        for (int j = 0; j < 4; j++) acc[i][j] = 0ull;

    for (int k0 = 0; k0 < K; k0 += BK) {
        // load A tile (BM x BK), transposed into As[k][m]
#pragma unroll
        for (int i = 0; i < 8; i++) {
            int idx = i * 256 + tid;
            int m = idx >> 4, kk = idx & 15;
            int gm = brow + m, gk = k0 + kk;
            As[kk][m] = (gm < M && gk < K) ? A[(size_t)gm * K + gk] : 0.f;
        }
        // load B tile (BK x BN)
#pragma unroll
        for (int i = 0; i < 8; i++) {
            int idx = i * 256 + tid;
            int kk = idx >> 7, n = idx & 127;
            int gk = k0 + kk, gn = bcol + n;
            Bs[kk][n] = (gk < K && gn < Ncols) ? B[(size_t)gk * Ncols + gn] : 0.f;
        }
        __syncthreads();

#pragma unroll
        for (int kk = 0; kk < BK; kk++) {
            float4 a0 = *(const float4*)&As[kk][ty * 8];
            float4 a1 = *(const float4*)&As[kk][ty * 8 + 4];
            float4 b0 = *(const float4*)&Bs[kk][tx * 8];
            float4 b1 = *(const float4*)&Bs[kk][tx * 8 + 4];
            unsigned long long bb0 = pack2(b0.x, b0.y);
            unsigned long long bb1 = pack2(b0.z, b0.w);
            unsigned long long bb2 = pack2(b1.x, b1.y);
            unsigned long long bb3 = pack2(b1.z, b1.w);
            float av[8] = {a0.x, a0.y, a0.z, a0.w, a1.x, a1.y, a1.z, a1.w};
#pragma unroll
            for (int i = 0; i < 8; i++) {
                unsigned long long aa = pack2(av[i], av[i]);
                fma2(acc[i][0], aa, bb0);
                fma2(acc[i][1], aa, bb1);
                fma2(acc[i][2], aa, bb2);
                fma2(acc[i][3], aa, bb3);
            }
        }
        __syncthreads();
    }

    // epilogue
#pragma unroll
    for (int i = 0; i < 8; i++) {
        int row = brow + ty * 8 + i;
        if (row >= M) continue;
        float rb = 0.f;
        if (MODE == 2) rb = rvec[row >> 9];
#pragma unroll
        for (int j = 0; j < 4; j++) {
            int col = bcol + tx * 8 + 2 * j;
            float2 v = unpack2(acc[i][j]);
            if (MODE == 1) {
                if (col < Ncols)     v.x += bias[col];
                if (col + 1 < Ncols) v.y += bias[col + 1];
            }
            if (MODE == 2) {
                if (col < Ncols)     v.x += rb * bias[col];
                if (col + 1 < Ncols) v.y += rb * bias[col + 1];
            }
            if (MODE >= 2) {            // relu for modes 2,3,4
                v.x = fmaxf(v.x, 0.f);
                v.y = fmaxf(v.y, 0.f);
            }
            if (MODE == 4) {
                // col even -> d=0, col+1 -> d=1, same b = col>>1
                if (col + 1 < Ncols) {
                    int b = col >> 1;
                    *(float2*)&C[(size_t)b * (NN * 2) + row * 2] = v;
                }
            } else {
                if (col + 1 < Ncols) {
                    *(float2*)&C[(size_t)row * Ncols + col] = v;
                } else if (col < Ncols) {
                    C[(size_t)row * Ncols + col] = v.x;
                }
            }
        }
    }
}

// ---------------- host launch ----------------
static float* symAddrF(const void* /*unused*/) { return nullptr; }

extern "C" void kernel_launch(void* const* d_in, const int* in_sizes, int n_in,
                              void* d_out, int out_size)
{
    const float* H   = (const float*)d_in[0];
    const float* smv = (const float*)d_in[1];
    const float* spv = (const float*)d_in[2];
    const float* W[6]  = {(const float*)d_in[3], (const float*)d_in[5], (const float*)d_in[7],
                          (const float*)d_in[9], (const float*)d_in[11], (const float*)d_in[13]};
    const float* bv[6] = {(const float*)d_in[4], (const float*)d_in[6], (const float*)d_in[8],
                          (const float*)d_in[10], (const float*)d_in[12], (const float*)d_in[14]};
    const int* smi = (const int*)d_in[15];
    const int* spi = (const int*)d_in[16];
    float* out = (float*)d_out;

    void *pP, *pQ, *pAsm, *pAsp, *pRsm, *pRsp;
    cudaGetSymbolAddress(&pP,   g_bufP);
    cudaGetSymbolAddress(&pQ,   g_bufQ);
    cudaGetSymbolAddress(&pAsm, g_Asm);
    cudaGetSymbolAddress(&pAsp, g_Asp);
    cudaGetSymbolAddress(&pRsm, g_rsm);
    cudaGetSymbolAddress(&pRsp, g_rsp);
    float* P   = (float*)pP;
    float* Q   = (float*)pQ;
    float* Am  = (float*)pAsm;
    float* Ap  = (float*)pAsp;
    float* rsm = (float*)pRsm;
    float* rsp = (float*)pRsp;

    // densify both Laplacians + row sums
    zero2_k<<<(NN*NN + 255) / 256, 256>>>(Am, Ap, NN*NN);
    scatter_k<<<(NNZK + 255) / 256, 256>>>(smi, smv, Am);
    scatter_k<<<(NNZK + 255) / 256, 256>>>(spi, spv, Ap);
    rowsums_k<<<1, 256>>>(Am, Ap, rsm, rsp);

    // H [B,N,2] -> P [N,B,2]
    transpose_in_k<<<(BB*NN + 255) / 256, 256>>>(H, P);

    auto grd = [](int M, int Nc) { return dim3((Nc + BN - 1) / BN, (M + BM - 1) / BM); };
    const int MR = NN * BB;  // 130560 rows for XW GEMMs

    // L0 (enc0, 2->400): DAD-first.  T = Asm @ X  (255 x 1024); then relu(T@W0 + r⊗b0)
    sgemm_k<0><<<grd(NN, 1024), 256>>>(Am, P, Q, NN, 1024, NN, nullptr, nullptr);
    sgemm_k<2><<<grd(MR, 400),  256>>>(Q, W[0], P, MR, 400, 2, bv[0], rsm);

    // L1 (enc1, 400->300): DAD-after. Y = X@W1+b1; X' = relu(Asm @ Y)
    sgemm_k<1><<<grd(MR, 300),     256>>>(P, W[1], Q, MR, 300, 400, bv[1], nullptr);
    sgemm_k<3><<<grd(NN, 153600),  256>>>(Am, Q, P, NN, 153600, NN, nullptr, nullptr);

    // L2 (enc2, 300->100): DAD-after.
    sgemm_k<1><<<grd(MR, 100),    256>>>(P, W[2], Q, MR, 100, 300, bv[2], nullptr);
    sgemm_k<3><<<grd(NN, 51200),  256>>>(Am, Q, P, NN, 51200, NN, nullptr, nullptr);

    // L3 (dec0, 100->300): DAD-first (sharpening matrix Asp).
    sgemm_k<0><<<grd(NN, 51200), 256>>>(Ap, P, Q, NN, 51200, NN, nullptr, nullptr);
    sgemm_k<2><<<grd(MR, 300),   256>>>(Q, W[3], P, MR, 300, 100, bv[3], rsp);

    // L4 (dec1, 300->400): DAD-first.
    sgemm_k<0><<<grd(NN, 153600), 256>>>(Ap, P, Q, NN, 153600, NN, nullptr, nullptr);
    sgemm_k<2><<<grd(MR, 400),    256>>>(Q, W[4], P, MR, 400, 300, bv[4], rsp);

    // L5 (dec2, 400->2): DAD-after; final GEMM scatters to [B,N,2] with relu.
    sgemm_k<1><<<grd(MR, 2),   256>>>(P, W[5], Q, MR, 2, 400, bv[5], nullptr);
    sgemm_k<4><<<grd(NN, 1024), 256>>>(Ap, Q, out, NN, 1024, NN, nullptr, nullptr);

    (void)in_sizes; (void)n_in; (void)out_size; (void)symAddrF;
}

// round 2
// speedup vs baseline: 1.2180x; 1.2180x over previous
#include <cuda_runtime.h>
#include <cuda_bf16.h>
#include <cstdint>

// Problem constants
#define NN   255          // nodes
#define BB   512          // batch
#define NNZK 2550
#define MAXD 400
#define MRR  (NN*BB)      // 130560 flattened rows
#define BIGBUF (MRR*MAXD) // 52,224,000 floats

// Scratch (device globals: allocation-free rule)
__device__ float g_bufP[BIGBUF];
__device__ float g_bufQ[BIGBUF];
__device__ float g_Asm[NN*NN];
__device__ float g_Asp[NN*NN];
__device__ float g_rsm[NN];
__device__ float g_rsp[NN];

// ---------------- f32x2 packed-FMA helpers (sm_103a) ----------------
__device__ __forceinline__ unsigned long long pack2(float x, float y) {
    unsigned long long r;
    asm("mov.b64 %0, {%1,%2};" : "=l"(r) : "f"(x), "f"(y));
    return r;
}
__device__ __forceinline__ void fma2(unsigned long long& acc,
                                     unsigned long long a, unsigned long long b) {
    asm("fma.rn.f32x2 %0, %1, %2, %0;" : "+l"(acc) : "l"(a), "l"(b));
}
__device__ __forceinline__ float2 unpack2(unsigned long long v) {
    float2 f;
    asm("mov.b64 {%0,%1}, %2;" : "=f"(f.x), "=f"(f.y) : "l"(v));
    return f;
}

// ---------------- small prep kernels ----------------
__global__ void zero2_k(float* a, float* b, int n) {
    int t = blockIdx.x * blockDim.x + threadIdx.x;
    if (t < n) { a[t] = 0.f; b[t] = 0.f; }
}

__global__ void scatter_k(const int* __restrict__ idx, const float* __restrict__ val,
                          float* __restrict__ A) {
    int t = blockIdx.x * blockDim.x + threadIdx.x;
    if (t < NNZK) atomicAdd(&A[idx[2*t] * NN + idx[2*t+1]], val[t]);
}

// warp-per-row rowsums for both matrices (510 warps)
__global__ void rowsums_k(const float* __restrict__ Am, const float* __restrict__ Ap,
                          float* __restrict__ rm, float* __restrict__ rp) {
    int w = (blockIdx.x * blockDim.x + threadIdx.x) >> 5;
    int lid = threadIdx.x & 31;
    if (w >= 2 * NN) return;
    const float* src = (w < NN) ? Am : Ap;
    int r = (w < NN) ? w : w - NN;
    float s = 0.f;
    for (int j = lid; j < NN; j += 32) s += src[r * NN + j];
#pragma unroll
    for (int o = 16; o; o >>= 1) s += __shfl_down_sync(~0u, s, o);
    if (lid == 0) ((w < NN) ? rm : rp)[r] = s;
}

// H [B,N,2] row-major -> X [N,B,2]
__global__ void transpose_in_k(const float* __restrict__ H, float* __restrict__ X) {
    int t = blockIdx.x * blockDim.x + threadIdx.x;
    if (t < BB * NN) {
        int b = t / NN, n = t % NN;
        float2 v = *(const float2*)&H[(size_t)t * 2];
        *(float2*)&X[((size_t)n * BB + b) * 2] = v;
    }
}

// L0 XW specialized: K=2. out[row][c] = relu(rsm[row>>9]*b0[c] + q0*W[0][c] + q1*W[1][c])
// Q: [MR][2], W: [2][400], out: [MR][400]. One thread -> 4 cols of one row.
__global__ __launch_bounds__(256)
void l0xw_k(const float* __restrict__ Q, const float* __restrict__ W,
            const float* __restrict__ bias, const float* __restrict__ rvec,
            float* __restrict__ out) {
    long long t = (long long)blockIdx.x * blockDim.x + threadIdx.x;
    if (t >= (long long)MRR * 100) return;
    int row = (int)(t / 100);
    int c   = (int)(t % 100) * 4;
    float2 q = *(const float2*)&Q[(size_t)row * 2];
    float rb = rvec[row >> 9];
    float4 w0 = *(const float4*)&W[c];
    float4 w1 = *(const float4*)&W[400 + c];
    float4 bv = *(const float4*)&bias[c];
    float4 o;
    o.x = fmaxf(fmaf(rb, bv.x, q.x * w0.x + q.y * w1.x), 0.f);
    o.y = fmaxf(fmaf(rb, bv.y, q.x * w0.y + q.y * w1.y), 0.f);
    o.z = fmaxf(fmaf(rb, bv.z, q.x * w0.z + q.y * w1.z), 0.f);
    o.w = fmaxf(fmaf(rb, bv.w, q.x * w0.w + q.y * w1.w), 0.f);
    *(float4*)&out[(size_t)row * 400 + c] = o;
}

// L5 XW specialized: Ncols=2, K=400. Warp-per-row dot products, + bias (no relu).
__global__ __launch_bounds__(256)
void l5xw_k(const float* __restrict__ P, const float* __restrict__ W,
            const float* __restrict__ bias, float* __restrict__ Q) {
    __shared__ float w[800];
    for (int i = threadIdx.x; i < 800; i += 256) w[i] = W[i];
    __syncthreads();
    int warp = (int)((blockIdx.x * blockDim.x + threadIdx.x) >> 5);
    int lid = threadIdx.x & 31;
    if (warp >= MRR) return;
    const float4* p4 = (const float4*)&P[(size_t)warp * 400];  // 100 float4
    float s0 = 0.f, s1 = 0.f;
#pragma unroll
    for (int rep = 0; rep < 3; rep++) {
        int j = lid + rep * 32;
        float4 v = p4[j];
        int k8 = j * 8;
        s0 += v.x * w[k8]   + v.y * w[k8+2] + v.z * w[k8+4] + v.w * w[k8+6];
        s1 += v.x * w[k8+1] + v.y * w[k8+3] + v.z * w[k8+5] + v.w * w[k8+7];
    }
    if (lid < 4) {
        int j = lid + 96;
        float4 v = p4[j];
        int k8 = j * 8;
        s0 += v.x * w[k8]   + v.y * w[k8+2] + v.z * w[k8+4] + v.w * w[k8+6];
        s1 += v.x * w[k8+1] + v.y * w[k8+3] + v.z * w[k8+5] + v.w * w[k8+7];
    }
#pragma unroll
    for (int o = 16; o; o >>= 1) {
        s0 += __shfl_down_sync(~0u, s0, o);
        s1 += __shfl_down_sync(~0u, s1, o);
    }
    if (lid == 0) {
        Q[(size_t)warp * 2]     = s0 + bias[0];
        Q[(size_t)warp * 2 + 1] = s1 + bias[1];
    }
}

// ---------------- pipelined tiled SGEMM with epilogue modes ----------------
// C[M,Ncols] = A[M,K] @ B[K,Ncols]   (all row-major)
// MODE 0: plain store
// MODE 1: + bias[col]
// MODE 2: + rvec[row>>9]*bias[col], relu
// MODE 3: relu
// MODE 4: relu, scatter-store to out[b*(N*2) + row*2 + d], col=(b*2+d), Ncols=1024
#define BM 128
#define BN 128
#define BK 16

template<int MODE>
__global__ __launch_bounds__(256, 2)
void sgemm_k(const float* __restrict__ A, const float* __restrict__ B,
             float* __restrict__ C, int M, int Ncols, int K,
             const float* __restrict__ bias, const float* __restrict__ rvec)
{
    __shared__ float As[2][BK][BM + 4];
    __shared__ float Bs[2][BK][BN + 4];

    const int tid  = threadIdx.x;
    const int tx   = tid & 15;
    const int ty   = tid >> 4;
    const int brow = blockIdx.y * BM;
    const int bcol = blockIdx.x * BN;

    unsigned long long acc[8][4];
#pragma unroll
    for (int i = 0; i < 8; i++)
#pragma unroll
        for (int j = 0; j < 4; j++) acc[i][j] = 0ull;

    float ra[8], rb[8];

    auto ldA = [&](int k0) {
#pragma unroll
        for (int i = 0; i < 8; i++) {
            int idx = i * 256 + tid;
            int m = idx >> 4, kk = idx & 15;
            int gm = brow + m, gk = k0 + kk;
            ra[i] = (gm < M && gk < K) ? A[(size_t)gm * K + gk] : 0.f;
        }
    };
    auto ldB = [&](int k0) {
#pragma unroll
        for (int i = 0; i < 8; i++) {
            int idx = i * 256 + tid;
            int kk = idx >> 7, n = idx & 127;
            int gk = k0 + kk, gn = bcol + n;
            rb[i] = (gk < K && gn < Ncols) ? B[(size_t)gk * Ncols + gn] : 0.f;
        }
    };
    auto stsA = [&](int bf) {
#pragma unroll
        for (int i = 0; i < 8; i++) {
            int idx = i * 256 + tid;
            As[bf][idx & 15][idx >> 4] = ra[i];
        }
    };
    auto stsB = [&](int bf) {
#pragma unroll
        for (int i = 0; i < 8; i++) {
            int idx = i * 256 + tid;
            Bs[bf][idx >> 7][idx & 127] = rb[i];
        }
    };

    const int S = (K + BK - 1) / BK;
    ldA(0); ldB(0);
    stsA(0); stsB(0);
    __syncthreads();

    int buf = 0;
    for (int s = 0; s < S; s++) {
        if (s + 1 < S) { ldA((s + 1) * BK); ldB((s + 1) * BK); }

#pragma unroll
        for (int kk = 0; kk < BK; kk++) {
            float4 a0 = *(const float4*)&As[buf][kk][ty * 8];
            float4 a1 = *(const float4*)&As[buf][kk][ty * 8 + 4];
            float4 b0 = *(const float4*)&Bs[buf][kk][tx * 8];
            float4 b1 = *(const float4*)&Bs[buf][kk][tx * 8 + 4];
            unsigned long long bb0 = pack2(b0.x, b0.y);
            unsigned long long bb1 = pack2(b0.z, b0.w);
            unsigned long long bb2 = pack2(b1.x, b1.y);
            unsigned long long bb3 = pack2(b1.z, b1.w);
            float av[8] = {a0.x, a0.y, a0.z, a0.w, a1.x, a1.y, a1.z, a1.w};
#pragma unroll
            for (int i = 0; i < 8; i++) {
                unsigned long long aa = pack2(av[i], av[i]);
                fma2(acc[i][0], aa, bb0);
                fma2(acc[i][1], aa, bb1);
                fma2(acc[i][2], aa, bb2);
                fma2(acc[i][3], aa, bb3);
            }
        }

        if (s + 1 < S) {
            stsA(buf ^ 1); stsB(buf ^ 1);
            __syncthreads();
            buf ^= 1;
        }
    }

    // epilogue
#pragma unroll
    for (int i = 0; i < 8; i++) {
        int row = brow + ty * 8 + i;
        if (row >= M) continue;
        float rb2 = 0.f;
        if (MODE == 2) rb2 = rvec[row >> 9];
#pragma unroll
        for (int j = 0; j < 4; j++) {
            int col = bcol + tx * 8 + 2 * j;
            float2 v = unpack2(acc[i][j]);
            if (MODE == 1) {
                if (col < Ncols)     v.x += bias[col];
                if (col + 1 < Ncols) v.y += bias[col + 1];
            }
            if (MODE == 2) {
                if (col < Ncols)     v.x += rb2 * bias[col];
                if (col + 1 < Ncols) v.y += rb2 * bias[col + 1];
            }
            if (MODE >= 2) {
                v.x = fmaxf(v.x, 0.f);
                v.y = fmaxf(v.y, 0.f);
            }
            if (MODE == 4) {
                if (col + 1 < Ncols) {
                    int b = col >> 1;
                    *(float2*)&C[(size_t)b * (NN * 2) + row * 2] = v;
                }
            } else {
                if (col + 1 < Ncols) {
                    *(float2*)&C[(size_t)row * Ncols + col] = v;
                } else if (col < Ncols) {
                    C[(size_t)row * Ncols + col] = v.x;
                }
            }
        }
    }
}

// ---------------- host launch ----------------
extern "C" void kernel_launch(void* const* d_in, const int* in_sizes, int n_in,
                              void* d_out, int out_size)
{
    const float* H   = (const float*)d_in[0];
    const float* smv = (const float*)d_in[1];
    const float* spv = (const float*)d_in[2];
    const float* W[6]  = {(const float*)d_in[3], (const float*)d_in[5], (const float*)d_in[7],
                          (const float*)d_in[9], (const float*)d_in[11], (const float*)d_in[13]};
    const float* bv[6] = {(const float*)d_in[4], (const float*)d_in[6], (const float*)d_in[8],
                          (const float*)d_in[10], (const float*)d_in[12], (const float*)d_in[14]};
    const int* smi = (const int*)d_in[15];
    const int* spi = (const int*)d_in[16];
    float* out = (float*)d_out;

    void *pP, *pQ, *pAsm, *pAsp, *pRsm, *pRsp;
    cudaGetSymbolAddress(&pP,   g_bufP);
    cudaGetSymbolAddress(&pQ,   g_bufQ);
    cudaGetSymbolAddress(&pAsm, g_Asm);
    cudaGetSymbolAddress(&pAsp, g_Asp);
    cudaGetSymbolAddress(&pRsm, g_rsm);
    cudaGetSymbolAddress(&pRsp, g_rsp);
    float* P   = (float*)pP;
    float* Q   = (float*)pQ;
    float* Am  = (float*)pAsm;
    float* Ap  = (float*)pAsp;
    float* rsm = (float*)pRsm;
    float* rsp = (float*)pRsp;

    // densify both Laplacians + row sums
    zero2_k<<<(NN*NN + 255) / 256, 256>>>(Am, Ap, NN*NN);
    scatter_k<<<(NNZK + 255) / 256, 256>>>(smi, smv, Am);
    scatter_k<<<(NNZK + 255) / 256, 256>>>(spi, spv, Ap);
    rowsums_k<<<(2 * NN * 32 + 255) / 256, 256>>>(Am, Ap, rsm, rsp);

    // H [B,N,2] -> P [N,B,2]
    transpose_in_k<<<(BB*NN + 255) / 256, 256>>>(H, P);

    auto grd = [](int M, int Nc) { return dim3((Nc + BN - 1) / BN, (M + BM - 1) / BM); };
    const int MR = MRR;

    // L0 (enc0, 2->400): DAD-first.  T = Asm @ X; then relu(T@W0 + r⊗b0) [specialized, K=2]
    sgemm_k<0><<<grd(NN, 1024), 256>>>(Am, P, Q, NN, 1024, NN, nullptr, nullptr);
    l0xw_k<<<((long long)MR * 100 + 255) / 256, 256>>>(Q, W[0], bv[0], rsm, P);

    // L1 (enc1, 400->300): DAD-after.
    sgemm_k<1><<<grd(MR, 300),     256>>>(P, W[1], Q, MR, 300, 400, bv[1], nullptr);
    sgemm_k<3><<<grd(NN, 153600),  256>>>(Am, Q, P, NN, 153600, NN, nullptr, nullptr);

    // L2 (enc2, 300->100): DAD-after.
    sgemm_k<1><<<grd(MR, 100),    256>>>(P, W[2], Q, MR, 100, 300, bv[2], nullptr);
    sgemm_k<3><<<grd(NN, 51200),  256>>>(Am, Q, P, NN, 51200, NN, nullptr, nullptr);

    // L3 (dec0, 100->300): DAD-first (sharpening matrix Asp).
    sgemm_k<0><<<grd(NN, 51200), 256>>>(Ap, P, Q, NN, 51200, NN, nullptr, nullptr);
    sgemm_k<2><<<grd(MR, 300),   256>>>(Q, W[3], P, MR, 300, 100, bv[3], rsp);

    // L4 (dec1, 300->400): DAD-first.
    sgemm_k<0><<<grd(NN, 153600), 256>>>(Ap, P, Q, NN, 153600, NN, nullptr, nullptr);
    sgemm_k<2><<<grd(MR, 400),    256>>>(Q, W[4], P, MR, 400, 300, bv[4], rsp);

    // L5 (dec2, 400->2): specialized row-dot (Ncols=2) then DAD scatter-store.
    l5xw_k<<<(MR * 32 + 255) / 256, 256>>>(P, W[5], bv[5], Q);
    sgemm_k<4><<<grd(NN, 1024), 256>>>(Ap, Q, out, NN, 1024, NN, nullptr, nullptr);

    (void)in_sizes; (void)n_in; (void)out_size;
}

// round 7
// speedup vs baseline: 1.4297x; 1.1738x over previous
#include <cuda_runtime.h>
#include <cuda_bf16.h>
#include <cstdint>

// Problem constants
#define NN   255          // nodes
#define BB   512          // batch
#define NNZK 2550
#define MAXD 400
#define MRR  (NN*BB)      // 130560 flattened rows
#define BIGBUF (MRR*MAXD) // 52,224,000 floats

// Scratch (device globals: allocation-free rule)
__device__ float g_bufP[BIGBUF];
__device__ float g_bufQ[BIGBUF];
__device__ float g_Asm[NN*NN];
__device__ float g_Asp[NN*NN];
__device__ float g_rsm[NN];
__device__ float g_rsp[NN];

// ---------------- f32x2 packed-FMA helpers (sm_103a) ----------------
__device__ __forceinline__ unsigned long long pack2(float x, float y) {
    unsigned long long r;
    asm("mov.b64 %0, {%1,%2};" : "=l"(r) : "f"(x), "f"(y));
    return r;
}
__device__ __forceinline__ void fma2(unsigned long long& acc,
                                     unsigned long long a, unsigned long long b) {
    asm("fma.rn.f32x2 %0, %1, %2, %0;" : "+l"(acc) : "l"(a), "l"(b));
}
__device__ __forceinline__ float2 unpack2(unsigned long long v) {
    float2 f;
    asm("mov.b64 {%0,%1}, %2;" : "=f"(f.x), "=f"(f.y) : "l"(v));
    return f;
}

// ---------------- small prep kernels ----------------
__global__ void zero2_k(float* a, float* b, int n) {
    int t = blockIdx.x * blockDim.x + threadIdx.x;
    if (t < n) { a[t] = 0.f; b[t] = 0.f; }
}

__global__ void scatter_k(const int* __restrict__ idx, const float* __restrict__ val,
                          float* __restrict__ A) {
    int t = blockIdx.x * blockDim.x + threadIdx.x;
    if (t < NNZK) atomicAdd(&A[idx[2*t] * NN + idx[2*t+1]], val[t]);
}

__global__ void rowsums_k(const float* __restrict__ Am, const float* __restrict__ Ap,
                          float* __restrict__ rm, float* __restrict__ rp) {
    int w = (blockIdx.x * blockDim.x + threadIdx.x) >> 5;
    int lid = threadIdx.x & 31;
    if (w >= 2 * NN) return;
    const float* src = (w < NN) ? Am : Ap;
    int r = (w < NN) ? w : w - NN;
    float s = 0.f;
    for (int j = lid; j < NN; j += 32) s += src[r * NN + j];
#pragma unroll
    for (int o = 16; o; o >>= 1) s += __shfl_down_sync(~0u, s, o);
    if (lid == 0) ((w < NN) ? rm : rp)[r] = s;
}

// H [B,N,2] row-major -> X [N,B,2]
__global__ void transpose_in_k(const float* __restrict__ H, float* __restrict__ X) {
    int t = blockIdx.x * blockDim.x + threadIdx.x;
    if (t < BB * NN) {
        int b = t / NN, n = t % NN;
        float2 v = *(const float2*)&H[(size_t)t * 2];
        *(float2*)&X[((size_t)n * BB + b) * 2] = v;
    }
}

// L0 XW specialized: K=2.
__global__ __launch_bounds__(256)
void l0xw_k(const float* __restrict__ Q, const float* __restrict__ W,
            const float* __restrict__ bias, const float* __restrict__ rvec,
            float* __restrict__ out) {
    long long t = (long long)blockIdx.x * blockDim.x + threadIdx.x;
    if (t >= (long long)MRR * 100) return;
    int row = (int)(t / 100);
    int c   = (int)(t % 100) * 4;
    float2 q = *(const float2*)&Q[(size_t)row * 2];
    float rb = rvec[row >> 9];
    float4 w0 = *(const float4*)&W[c];
    float4 w1 = *(const float4*)&W[400 + c];
    float4 bv = *(const float4*)&bias[c];
    float4 o;
    o.x = fmaxf(fmaf(rb, bv.x, q.x * w0.x + q.y * w1.x), 0.f);
    o.y = fmaxf(fmaf(rb, bv.y, q.x * w0.y + q.y * w1.y), 0.f);
    o.z = fmaxf(fmaf(rb, bv.z, q.x * w0.z + q.y * w1.z), 0.f);
    o.w = fmaxf(fmaf(rb, bv.w, q.x * w0.w + q.y * w1.w), 0.f);
    *(float4*)&out[(size_t)row * 400 + c] = o;
}

// L5 XW specialized: Ncols=2, K=400. Warp-per-row dot products, + bias.
__global__ __launch_bounds__(256)
void l5xw_k(const float* __restrict__ P, const float* __restrict__ W,
            const float* __restrict__ bias, float* __restrict__ Q) {
    __shared__ float w[800];
    for (int i = threadIdx.x; i < 800; i += 256) w[i] = W[i];
    __syncthreads();
    int warp = (int)((blockIdx.x * blockDim.x + threadIdx.x) >> 5);
    int lid = threadIdx.x & 31;
    if (warp >= MRR) return;
    const float4* p4 = (const float4*)&P[(size_t)warp * 400];
    float s0 = 0.f, s1 = 0.f;
#pragma unroll
    for (int rep = 0; rep < 3; rep++) {
        int j = lid + rep * 32;
        float4 v = p4[j];
        int k8 = j * 8;
        s0 += v.x * w[k8]   + v.y * w[k8+2] + v.z * w[k8+4] + v.w * w[k8+6];
        s1 += v.x * w[k8+1] + v.y * w[k8+3] + v.z * w[k8+5] + v.w * w[k8+7];
    }
    if (lid < 4) {
        int j = lid + 96;
        float4 v = p4[j];
        int k8 = j * 8;
        s0 += v.x * w[k8]   + v.y * w[k8+2] + v.z * w[k8+4] + v.w * w[k8+6];
        s1 += v.x * w[k8+1] + v.y * w[k8+3] + v.z * w[k8+5] + v.w * w[k8+7];
    }
#pragma unroll
    for (int o = 16; o; o >>= 1) {
        s0 += __shfl_down_sync(~0u, s0, o);
        s1 += __shfl_down_sync(~0u, s1, o);
    }
    if (lid == 0) {
        Q[(size_t)warp * 2]     = s0 + bias[0];
        Q[(size_t)warp * 2 + 1] = s1 + bias[1];
    }
}

// ---------------- cp.async pipelined SGEMM ----------------
// C[M,Ncols] = A[M,K] @ B[K,Ncols]   (row-major). Requires Ncols % 4 == 0
// MODE 0: store | 1: +bias | 2: +rvec[row>>9]*bias, relu | 3: relu | 4: relu+scatter [B,N,2]
#define BM 128
#define BN 128
#define BK 16

__device__ __forceinline__ void cp16(uint32_t dst, const float* src, bool p) {
    int sz = p ? 16 : 0;
    asm volatile("cp.async.cg.shared.global [%0], [%1], 16, %2;\n"
                 :: "r"(dst), "l"(src), "r"(sz));
}

template<int MODE>
__global__ __launch_bounds__(256, 2)
void sgemm_k(const float* __restrict__ A, const float* __restrict__ B,
             float* __restrict__ C, int M, int Ncols, int K,
             const float* __restrict__ bias, const float* __restrict__ rvec)
{
    __shared__ float As[2][BK][BM + 4];
    __shared__ float Bs[2][BK][BN + 4];

    const int tid  = threadIdx.x;
    const int tx   = tid & 15;
    const int ty   = tid >> 4;
    const int brow = blockIdx.y * BM;
    const int bcol = blockIdx.x * BN;

    unsigned long long acc[8][4];
#pragma unroll
    for (int i = 0; i < 8; i++)
#pragma unroll
        for (int j = 0; j < 4; j++) acc[i][j] = 0ull;

    float ra[8];

    // A tile load (registers, will be transposed into smem)
    auto ldA = [&](int k0) {
#pragma unroll
        for (int i = 0; i < 8; i++) {
            int idx = i * 256 + tid;
            int m = idx >> 4, kk = idx & 15;
            int gm = brow + m, gk = k0 + kk;
            ra[i] = (gm < M && gk < K) ? A[(size_t)gm * K + gk] : 0.f;
        }
    };
    auto stsA = [&](int bf) {
#pragma unroll
        for (int i = 0; i < 8; i++) {
            int idx = i * 256 + tid;
            As[bf][idx & 15][idx >> 4] = ra[i];
        }
    };
    // B tile via cp.async: 16 rows x 128 cols; per thread 2x 16B chunks
    const int brow16 = tid >> 5;       // 0..7
    const int bchunk = tid & 31;       // 0..31
    auto cpB = [&](int k0, int bf) {
        uint32_t base = (uint32_t)__cvta_generic_to_shared(&Bs[bf][0][0]);
#pragma unroll
        for (int i = 0; i < 2; i++) {
            int row = brow16 + i * 8;
            int gk = k0 + row, gn = bcol + bchunk * 4;
            bool p = (gk < K) && (gn < Ncols);
            const float* src = &B[(size_t)(p ? gk : 0) * Ncols + (p ? gn : 0)];
            uint32_t dst = base + (uint32_t)(row * (BN + 4) + bchunk * 4) * 4u;
            cp16(dst, src, p);
        }
    };

    const int S = (K + BK - 1) / BK;
    ldA(0);
    cpB(0, 0);
    asm volatile("cp.async.commit_group;");
    stsA(0);
    asm volatile("cp.async.wait_group 0;");
    __syncthreads();

    int buf = 0;
    for (int s = 0; s < S; s++) {
        if (s + 1 < S) {
            cpB((s + 1) * BK, buf ^ 1);
            asm volatile("cp.async.commit_group;");
            ldA((s + 1) * BK);
        }

#pragma unroll
        for (int kk = 0; kk < BK; kk++) {
            float4 a0 = *(const float4*)&As[buf][kk][ty * 8];
            float4 a1 = *(const float4*)&As[buf][kk][ty * 8 + 4];
            float4 b0 = *(const float4*)&Bs[buf][kk][tx * 8];
            float4 b1 = *(const float4*)&Bs[buf][kk][tx * 8 + 4];
            unsigned long long bb0 = pack2(b0.x, b0.y);
            unsigned long long bb1 = pack2(b0.z, b0.w);
            unsigned long long bb2 = pack2(b1.x, b1.y);
            unsigned long long bb3 = pack2(b1.z, b1.w);
            float av[8] = {a0.x, a0.y, a0.z, a0.w, a1.x, a1.y, a1.z, a1.w};
#pragma unroll
            for (int i = 0; i < 8; i++) {
                unsigned long long aa = pack2(av[i], av[i]);
                fma2(acc[i][0], aa, bb0);
                fma2(acc[i][1], aa, bb1);
                fma2(acc[i][2], aa, bb2);
                fma2(acc[i][3], aa, bb3);
            }
        }

        if (s + 1 < S) {
            stsA(buf ^ 1);
            asm volatile("cp.async.wait_group 0;");
            __syncthreads();
            buf ^= 1;
        }
    }

    // epilogue
#pragma unroll
    for (int i = 0; i < 8; i++) {
        int row = brow + ty * 8 + i;
        if (row >= M) continue;
        float rb2 = 0.f;
        if (MODE == 2) rb2 = rvec[row >> 9];
#pragma unroll
        for (int j = 0; j < 4; j++) {
            int col = bcol + tx * 8 + 2 * j;
            float2 v = unpack2(acc[i][j]);
            if (MODE == 1) {
                if (col < Ncols)     v.x += bias[col];
                if (col + 1 < Ncols) v.y += bias[col + 1];
            }
            if (MODE == 2) {
                if (col < Ncols)     v.x += rb2 * bias[col];
                if (col + 1 < Ncols) v.y += rb2 * bias[col + 1];
            }
            if (MODE >= 2) {
                v.x = fmaxf(v.x, 0.f);
                v.y = fmaxf(v.y, 0.f);
            }
            if (MODE == 4) {
                if (col + 1 < Ncols) {
                    int b = col >> 1;
                    *(float2*)&C[(size_t)b * (NN * 2) + row * 2] = v;
                }
            } else {
                if (col + 1 < Ncols) {
                    *(float2*)&C[(size_t)row * Ncols + col] = v;
                } else if (col < Ncols) {
                    C[(size_t)row * Ncols + col] = v.x;
                }
            }
        }
    }
}

// ---------------- host launch ----------------
extern "C" void kernel_launch(void* const* d_in, const int* in_sizes, int n_in,
                              void* d_out, int out_size)
{
    const float* H   = (const float*)d_in[0];
    const float* smv = (const float*)d_in[1];
    const float* spv = (const float*)d_in[2];
    const float* W[6]  = {(const float*)d_in[3], (const float*)d_in[5], (const float*)d_in[7],
                          (const float*)d_in[9], (const float*)d_in[11], (const float*)d_in[13]};
    const float* bv[6] = {(const float*)d_in[4], (const float*)d_in[6], (const float*)d_in[8],
                          (const float*)d_in[10], (const float*)d_in[12], (const float*)d_in[14]};
    const int* smi = (const int*)d_in[15];
    const int* spi = (const int*)d_in[16];
    float* out = (float*)d_out;

    void *pP, *pQ, *pAsm, *pAsp, *pRsm, *pRsp;
    cudaGetSymbolAddress(&pP,   g_bufP);
    cudaGetSymbolAddress(&pQ,   g_bufQ);
    cudaGetSymbolAddress(&pAsm, g_Asm);
    cudaGetSymbolAddress(&pAsp, g_Asp);
    cudaGetSymbolAddress(&pRsm, g_rsm);
    cudaGetSymbolAddress(&pRsp, g_rsp);
    float* P   = (float*)pP;
    float* Q   = (float*)pQ;
    float* Am  = (float*)pAsm;
    float* Ap  = (float*)pAsp;
    float* rsm = (float*)pRsm;
    float* rsp = (float*)pRsp;

    zero2_k<<<(NN*NN + 255) / 256, 256>>>(Am, Ap, NN*NN);
    scatter_k<<<(NNZK + 255) / 256, 256>>>(smi, smv, Am);
    scatter_k<<<(NNZK + 255) / 256, 256>>>(spi, spv, Ap);
    rowsums_k<<<(2 * NN * 32 + 255) / 256, 256>>>(Am, Ap, rsm, rsp);

    transpose_in_k<<<(BB*NN + 255) / 256, 256>>>(H, P);

    auto grd = [](int M, int Nc) { return dim3((Nc + BN - 1) / BN, (M + BM - 1) / BM); };
    const int MR = MRR;

    // L0 (enc0, 2->400): DAD-first; XW specialized (K=2)
    sgemm_k<0><<<grd(NN, 1024), 256>>>(Am, P, Q, NN, 1024, NN, nullptr, nullptr);
    l0xw_k<<<((long long)MR * 100 + 255) / 256, 256>>>(Q, W[0], bv[0], rsm, P);

    // L1 (enc1, 400->300): DAD-after.
    sgemm_k<1><<<grd(MR, 300),     256>>>(P, W[1], Q, MR, 300, 400, bv[1], nullptr);
    sgemm_k<3><<<grd(NN, 153600),  256>>>(Am, Q, P, NN, 153600, NN, nullptr, nullptr);

    // L2 (enc2, 300->100): DAD-after.
    sgemm_k<1><<<grd(MR, 100),    256>>>(P, W[2], Q, MR, 100, 300, bv[2], nullptr);
    sgemm_k<3><<<grd(NN, 51200),  256>>>(Am, Q, P, NN, 51200, NN, nullptr, nullptr);

    // L3 (dec0, 100->300): DAD-first.
    sgemm_k<0><<<grd(NN, 51200), 256>>>(Ap, P, Q, NN, 51200, NN, nullptr, nullptr);
    sgemm_k<2><<<grd(MR, 300),   256>>>(Q, W[3], P, MR, 300, 100, bv[3], rsp);

    // L4 (dec1, 300->400): DAD-first.
    sgemm_k<0><<<grd(NN, 153600), 256>>>(Ap, P, Q, NN, 153600, NN, nullptr, nullptr);
    sgemm_k<2><<<grd(MR, 400),    256>>>(Q, W[4], P, MR, 400, 300, bv[4], rsp);

    // L5 (dec2, 400->2): specialized row-dot then DAD scatter-store.
    l5xw_k<<<(MR * 32 + 255) / 256, 256>>>(P, W[5], bv[5], Q);
    sgemm_k<4><<<grd(NN, 1024), 256>>>(Ap, Q, out, NN, 1024, NN, nullptr, nullptr);

    (void)in_sizes; (void)n_in; (void)out_size;
}